// round 4
// baseline (speedup 1.0000x reference)
#include <cuda_runtime.h>
#include <math.h>

#define DHID 1024
#define DFF  4096
#define NE   8
#define TMAX 8192   // max tokens (B*S)
#define BM 64
#define BN 64
#define BK 16

// Scratch: h activations, pair-addressed (pair = token*2 + rank), max 2*T rows.
__device__ float d_h[(size_t)(2 * TMAX) * DFF];     // 268 MB
__device__ int   d_list [NE * TMAX];                // per-expert pair list
__device__ float d_wlist[NE * TMAX];                // per-entry gate weight
__device__ int   d_cnt[NE];
__device__ float d_usage[NE];

// ---------------- init: zero out + counters ----------------
__global__ void init_kernel(float* __restrict__ out, int n4) {
    int i = blockIdx.x * blockDim.x + threadIdx.x;
    if (i < NE) { d_cnt[i] = 0; d_usage[i] = 0.f; }
    if (i < n4) {
        ((float4*)out)[i] = make_float4(0.f, 0.f, 0.f, 0.f);
    }
}

// ---------------- gating: logits, top-2, softmax, dispatch ----------------
__global__ void gate_kernel(const float* __restrict__ x,
                            const float* __restrict__ Wg, int T) {
    int gwarp = (blockIdx.x * blockDim.x + threadIdx.x) >> 5;
    int lane  = threadIdx.x & 31;
    if (gwarp >= T) return;
    const float* xr = x + (size_t)gwarp * DHID;
    float acc[NE];
#pragma unroll
    for (int e = 0; e < NE; e++) acc[e] = 0.f;
    for (int d = lane; d < DHID; d += 32) {
        float xv = xr[d];
#pragma unroll
        for (int e = 0; e < NE; e++) acc[e] += xv * Wg[e * DHID + d];
    }
#pragma unroll
    for (int e = 0; e < NE; e++)
#pragma unroll
        for (int off = 16; off; off >>= 1)
            acc[e] += __shfl_xor_sync(0xffffffffu, acc[e], off);
    if (lane == 0) {
        // top-2 (ties -> lower index, matching jax top_k)
        float v0 = acc[0], v1 = -INFINITY;
        int i0 = 0, i1 = -1;
#pragma unroll
        for (int e = 1; e < NE; e++) {
            float v = acc[e];
            if (v > v0) { v1 = v0; i1 = i0; v0 = v; i0 = e; }
            else if (v > v1) { v1 = v; i1 = e; }
        }
        float e1 = __expf(v1 - v0);
        float inv = 1.f / (1.f + e1);
        float w0 = inv, w1 = e1 * inv;
        atomicAdd(&d_usage[i0], w0);
        atomicAdd(&d_usage[i1], w1);
        int p0 = atomicAdd(&d_cnt[i0], 1);
        d_list [i0 * TMAX + p0] = gwarp * 2 + 0;
        d_wlist[i0 * TMAX + p0] = w0;
        int p1 = atomicAdd(&d_cnt[i1], 1);
        d_list [i1 * TMAX + p1] = gwarp * 2 + 1;
        d_wlist[i1 * TMAX + p1] = w1;
    }
}

// ---------------- stage 1: h = gelu(gather(x) @ W1[e] + b1[e]) ----------------
__global__ __launch_bounds__(256)
void ffn1_kernel(const float* __restrict__ x, const float* __restrict__ W1,
                 const float* __restrict__ b1) {
    int e = blockIdx.z;
    int n = d_cnt[e];
    int row0 = blockIdx.y * BM;
    if (row0 >= n) return;
    int col0 = blockIdx.x * BN;

    __shared__ float As[BK][BM + 1];
    __shared__ float Bs[BK][BN];
    __shared__ int   sm_pair[BM];
    __shared__ int   sm_tok[BM];

    int tid = threadIdx.x;
    if (tid < BM) {
        int r = row0 + tid;
        int p = (r < n) ? d_list[e * TMAX + r] : -1;
        sm_pair[tid] = p;
        sm_tok[tid]  = (p >= 0) ? (p >> 1) : 0;
    }
    __syncthreads();

    float acc[4][4] = {};
    int tx = tid & 15, ty = tid >> 4;
    const float* Wb = W1 + (size_t)e * DHID * DFF;

    for (int k0 = 0; k0 < DHID; k0 += BK) {
#pragma unroll
        for (int i = 0; i < 4; i++) {
            int lin = tid + i * 256;
            int m = lin >> 4, k = lin & 15;
            As[k][m] = x[(size_t)sm_tok[m] * DHID + k0 + k];
        }
#pragma unroll
        for (int i = 0; i < 4; i++) {
            int lin = tid + i * 256;
            int k = lin >> 6, f = lin & 63;
            Bs[k][f] = Wb[(size_t)(k0 + k) * DFF + col0 + f];
        }
        __syncthreads();
#pragma unroll
        for (int k = 0; k < BK; k++) {
            float a[4];
#pragma unroll
            for (int i = 0; i < 4; i++) a[i] = As[k][ty * 4 + i];
            float4 b4 = *(const float4*)&Bs[k][tx * 4];
            float b[4] = {b4.x, b4.y, b4.z, b4.w};
#pragma unroll
            for (int i = 0; i < 4; i++)
#pragma unroll
                for (int j = 0; j < 4; j++) acc[i][j] += a[i] * b[j];
        }
        __syncthreads();
    }

#pragma unroll
    for (int i = 0; i < 4; i++) {
        int m = ty * 4 + i;
        int p = sm_pair[m];
        if (p < 0) continue;
        float* hrow = d_h + (size_t)p * DFF;
#pragma unroll
        for (int j = 0; j < 4; j++) {
            int c = col0 + tx * 4 + j;
            float v = acc[i][j] + b1[e * DFF + c];
            v = 0.5f * v * (1.f + erff(v * 0.70710678118654752f));
            hrow[c] = v;
        }
    }
}

// ---------------- stage 2: out[t] += w * (h @ W2[e] + b2[e]) ----------------
__global__ __launch_bounds__(256)
void ffn2_kernel(const float* __restrict__ W2, const float* __restrict__ b2,
                 float* __restrict__ out) {
    int e = blockIdx.z;
    int n = d_cnt[e];
    int row0 = blockIdx.y * BM;
    if (row0 >= n) return;
    int col0 = blockIdx.x * BN;

    __shared__ float As[BK][BM + 1];
    __shared__ float Bs[BK][BN];
    __shared__ int   sm_pair[BM];
    __shared__ float sm_w[BM];

    int tid = threadIdx.x;
    if (tid < BM) {
        int r = row0 + tid;
        if (r < n) { sm_pair[tid] = d_list[e * TMAX + r]; sm_w[tid] = d_wlist[e * TMAX + r]; }
        else       { sm_pair[tid] = -1; sm_w[tid] = 0.f; }
    }
    __syncthreads();

    float acc[4][4] = {};
    int tx = tid & 15, ty = tid >> 4;
    const float* Wb = W2 + (size_t)e * DFF * DHID;

    for (int k0 = 0; k0 < DFF; k0 += BK) {
#pragma unroll
        for (int i = 0; i < 4; i++) {
            int lin = tid + i * 256;
            int m = lin >> 4, k = lin & 15;
            int p = sm_pair[m];
            As[k][m] = (p >= 0) ? d_h[(size_t)p * DFF + k0 + k] : 0.f;
        }
#pragma unroll
        for (int i = 0; i < 4; i++) {
            int lin = tid + i * 256;
            int k = lin >> 6, f = lin & 63;
            Bs[k][f] = Wb[(size_t)(k0 + k) * DHID + col0 + f];
        }
        __syncthreads();
#pragma unroll
        for (int k = 0; k < BK; k++) {
            float a[4];
#pragma unroll
            for (int i = 0; i < 4; i++) a[i] = As[k][ty * 4 + i];
            float4 b4 = *(const float4*)&Bs[k][tx * 4];
            float b[4] = {b4.x, b4.y, b4.z, b4.w};
#pragma unroll
            for (int i = 0; i < 4; i++)
#pragma unroll
                for (int j = 0; j < 4; j++) acc[i][j] += a[i] * b[j];
        }
        __syncthreads();
    }

#pragma unroll
    for (int i = 0; i < 4; i++) {
        int m = ty * 4 + i;
        int p = sm_pair[m];
        if (p < 0) continue;
        int t = p >> 1;
        float w = sm_w[m];
        float* orow = out + (size_t)t * DHID;
#pragma unroll
        for (int j = 0; j < 4; j++) {
            int c = col0 + tx * 4 + j;
            float v = w * (acc[i][j] + b2[e * DHID + c]);
            atomicAdd(&orow[c], v);
        }
    }
}

// ---------------- lb loss ----------------
__global__ void lb_kernel(float* __restrict__ out, int bsd, int out_size, int T) {
    if (threadIdx.x == 0 && blockIdx.x == 0) {
        float u[NE], s = 0.f;
#pragma unroll
        for (int e = 0; e < NE; e++) { u[e] = d_usage[e] / (float)T; s += u[e]; }
        float mean = s / (float)NE;
        float v = 0.f;
#pragma unroll
        for (int e = 0; e < NE; e++) { float d = u[e] - mean; v += d * d; }
        v = v / (float)(NE - 1) * 0.01f;
        if (out_size > bsd) out[bsd] = v;
    }
}

extern "C" void kernel_launch(void* const* d_in, const int* in_sizes, int n_in,
                              void* d_out, int out_size) {
    const float* x  = (const float*)d_in[0];
    const float* Wg = (const float*)d_in[1];
    const float* W1 = (const float*)d_in[2];
    const float* b1 = (const float*)d_in[3];
    const float* W2 = (const float*)d_in[4];
    const float* b2 = (const float*)d_in[5];
    float* out = (float*)d_out;

    int T = in_sizes[0] / DHID;   // 8192
    int bsd = T * DHID;
    int n4 = bsd / 4;

    init_kernel<<<(n4 + 255) / 256, 256>>>(out, n4);
    gate_kernel<<<(T * 32 + 255) / 256, 256>>>(x, Wg, T);

    dim3 g1(DFF / BN, (T + BM - 1) / BM, NE);
    ffn1_kernel<<<g1, 256>>>(x, W1, b1);

    dim3 g2(DHID / BN, (T + BM - 1) / BM, NE);
    ffn2_kernel<<<g2, 256>>>(W2, b2, out);

    lb_kernel<<<1, 32>>>(out, bsd, out_size, T);
}

// round 14
// speedup vs baseline: 2.8251x; 2.8251x over previous
#include <cuda_runtime.h>
#include <cuda_bf16.h>
#include <math.h>
#include <stdint.h>

#define DHID 1024
#define DFF  4096
#define NE   8
#define TMAX 8192
#define BM 128
#define BN 128
#define BK 32
#define PADB 80                      // bytes per smem row (64 data + 16 pad; conflict-free)
#define TILE_B (128 * PADB)          // 10240 bytes per tile

// -------------------- device scratch (16B aligned) --------------------
__device__ __align__(16) __nv_bfloat16 d_xhi[(size_t)TMAX * DHID];
__device__ __align__(16) __nv_bfloat16 d_xlo[(size_t)TMAX * DHID];
__device__ __align__(16) __nv_bfloat16 d_w1hi[(size_t)NE * DFF * DHID];  // [e][f][d]
__device__ __align__(16) __nv_bfloat16 d_w1lo[(size_t)NE * DFF * DHID];
__device__ __align__(16) __nv_bfloat16 d_w2hi[(size_t)NE * DHID * DFF]; // [e][d][f]
__device__ __align__(16) __nv_bfloat16 d_w2lo[(size_t)NE * DHID * DFF];
__device__ __align__(16) __nv_bfloat16 d_hhi[(size_t)(2 * TMAX) * DFF]; // pair-addressed
__device__ __align__(16) __nv_bfloat16 d_hlo[(size_t)(2 * TMAX) * DFF];
__device__ int   d_list [NE * TMAX];
__device__ float d_wlist[NE * TMAX];
__device__ int   d_cnt[NE];
__device__ float d_usage[NE];

// -------------------- helpers --------------------
#define MMA16816(d, a, b0, b1) \
    asm volatile("mma.sync.aligned.m16n8k16.row.col.f32.bf16.bf16.f32 " \
        "{%0,%1,%2,%3},{%4,%5,%6,%7},{%8,%9},{%0,%1,%2,%3};" \
        : "+f"((d)[0]), "+f"((d)[1]), "+f"((d)[2]), "+f"((d)[3]) \
        : "r"((a)[0]), "r"((a)[1]), "r"((a)[2]), "r"((a)[3]), "r"(b0), "r"(b1))

__device__ __forceinline__ float gelu_exact(float v) {
    return 0.5f * v * (1.f + erff(v * 0.70710678118654752f));
}
__device__ __forceinline__ void bsplit(float v, __nv_bfloat16& h, __nv_bfloat16& l) {
    h = __float2bfloat16(v);
    l = __float2bfloat16(v - __bfloat162float(h));
}

// -------------------- init --------------------
__global__ void init_kernel(float* __restrict__ out, int n4) {
    int i = blockIdx.x * blockDim.x + threadIdx.x;
    if (i < NE) { d_cnt[i] = 0; d_usage[i] = 0.f; }
    if (i < n4) ((float4*)out)[i] = make_float4(0.f, 0.f, 0.f, 0.f);
}

// -------------------- gating --------------------
__global__ void gate_kernel(const float* __restrict__ x,
                            const float* __restrict__ Wg, int T) {
    int gwarp = (blockIdx.x * blockDim.x + threadIdx.x) >> 5;
    int lane  = threadIdx.x & 31;
    if (gwarp >= T) return;
    const float* xr = x + (size_t)gwarp * DHID;
    float acc[NE];
#pragma unroll
    for (int e = 0; e < NE; e++) acc[e] = 0.f;
    for (int d = lane; d < DHID; d += 32) {
        float xv = xr[d];
#pragma unroll
        for (int e = 0; e < NE; e++) acc[e] += xv * Wg[e * DHID + d];
    }
#pragma unroll
    for (int e = 0; e < NE; e++)
#pragma unroll
        for (int off = 16; off; off >>= 1)
            acc[e] += __shfl_xor_sync(0xffffffffu, acc[e], off);
    if (lane == 0) {
        float v0 = acc[0], v1 = -INFINITY;
        int i0 = 0, i1 = -1;
#pragma unroll
        for (int e = 1; e < NE; e++) {
            float v = acc[e];
            if (v > v0) { v1 = v0; i1 = i0; v0 = v; i0 = e; }
            else if (v > v1) { v1 = v; i1 = e; }
        }
        float e1 = __expf(v1 - v0);
        float inv = 1.f / (1.f + e1);
        float w0 = inv, w1 = e1 * inv;
        atomicAdd(&d_usage[i0], w0);
        atomicAdd(&d_usage[i1], w1);
        int p0 = atomicAdd(&d_cnt[i0], 1);
        d_list [i0 * TMAX + p0] = gwarp * 2 + 0;
        d_wlist[i0 * TMAX + p0] = w0;
        int p1 = atomicAdd(&d_cnt[i1], 1);
        d_list [i1 * TMAX + p1] = gwarp * 2 + 1;
        d_wlist[i1 * TMAX + p1] = w1;
    }
}

// -------------------- x -> bf16 hi/lo --------------------
__global__ void conv_x(const float* __restrict__ x, int n) {
    int i = blockIdx.x * blockDim.x + threadIdx.x;
    if (i >= n) return;
    float v = x[i];
    __nv_bfloat16 h, l; bsplit(v, h, l);
    d_xhi[i] = h; d_xlo[i] = l;
}

// -------- W [e][R][C] -> W^T [e][C][R], bf16 hi/lo split --------
template<bool ISW1>
__global__ void trans_conv(const float* __restrict__ in) {
    const int R = ISW1 ? DHID : DFF;
    const int C = ISW1 ? DFF : DHID;
    __nv_bfloat16* oh = ISW1 ? d_w1hi : d_w2hi;
    __nv_bfloat16* ol = ISW1 ? d_w1lo : d_w2lo;
    __shared__ float t[32][33];
    int e = blockIdx.z;
    const float* ip = in + (size_t)e * R * C;
    size_t ob = (size_t)e * R * C;
    int c0 = blockIdx.x * 32, r0 = blockIdx.y * 32;
    int tx = threadIdx.x, ty = threadIdx.y;
#pragma unroll
    for (int i = 0; i < 32; i += 8)
        t[ty + i][tx] = ip[(size_t)(r0 + ty + i) * C + c0 + tx];
    __syncthreads();
#pragma unroll
    for (int i = 0; i < 32; i += 8) {
        float v = t[tx][ty + i];
        __nv_bfloat16 h, l; bsplit(v, h, l);
        size_t o = ob + (size_t)(c0 + ty + i) * R + r0 + tx;
        oh[o] = h; ol[o] = l;
    }
}

// -------------------- fused FFN GEMM: bf16x3 on mma.sync, manual fragments --------------------
template<int KTOT, bool FFN1>
__global__ void __launch_bounds__(256)
ffn_mma(const float* __restrict__ bias, float* __restrict__ outp)
{
    __shared__ __align__(16) char sm[4 * TILE_B];     // Ahi | Alo | Bhi | Blo
    __shared__ int   sm_row[BM];
    __shared__ int   sm_pair[BM];
    __shared__ float sm_w[BM];

    int e = blockIdx.z;
    int n = d_cnt[e];
    int row0 = blockIdx.y * BM;
    if (row0 >= n) return;
    int col0 = blockIdx.x * BN;

    int tid = threadIdx.x;
    if (tid < BM) {
        int r = row0 + tid;
        int rc = (r < n) ? r : (n - 1);
        int p = d_list[e * TMAX + rc];
        sm_row[tid]  = FFN1 ? (p >> 1) : p;
        sm_pair[tid] = (r < n) ? p : -1;
        sm_w[tid]    = (r < n) ? d_wlist[e * TMAX + r] : 0.f;
    }
    __syncthreads();

    const __nv_bfloat16* Ah = FFN1 ? d_xhi : d_hhi;
    const __nv_bfloat16* Al = FFN1 ? d_xlo : d_hlo;
    const __nv_bfloat16* Bh = (FFN1 ? d_w1hi : d_w2hi) + (size_t)e * DFF * DHID + (size_t)col0 * KTOT;
    const __nv_bfloat16* Bl = (FFN1 ? d_w1lo : d_w2lo) + (size_t)e * DFF * DHID + (size_t)col0 * KTOT;
    const float* be = bias + (size_t)e * (FFN1 ? DFF : DHID);

    float acc[4][4][4] = {};
    uint4 pf[8];

    // initial prefetch (k0 = 0)
#pragma unroll
    for (int i = 0; i < 8; i++) {
        int idx = tid + i * 256;
        int tile = idx >> 9, w = idx & 511, rr = w >> 2, c = w & 3;
        size_t off = (size_t)(c * 8);
        const __nv_bfloat16* src =
            (tile == 0) ? Ah + (size_t)sm_row[rr] * KTOT + off :
            (tile == 1) ? Al + (size_t)sm_row[rr] * KTOT + off :
            (tile == 2) ? Bh + (size_t)rr * KTOT + off :
                          Bl + (size_t)rr * KTOT + off;
        pf[i] = *(const uint4*)src;
    }

    const int KT = KTOT / BK;
    int lane = tid & 31, wid = tid >> 5;
    int wm = wid >> 2, wn = wid & 3;              // 2(m) x 4(n) warps; warp tile 64x32
    int g = lane >> 2, q = lane & 3;

    for (int it = 0; it < KT; it++) {
        // store prefetched tile
#pragma unroll
        for (int i = 0; i < 8; i++) {
            int idx = tid + i * 256;
            int tile = idx >> 9, w = idx & 511, rr = w >> 2, c = w & 3;
            *(uint4*)(sm + tile * TILE_B + rr * PADB + c * 16) = pf[i];
        }
        __syncthreads();
        // prefetch next tile into regs (overlaps with compute)
        if (it + 1 < KT) {
            int k0 = (it + 1) * BK;
#pragma unroll
            for (int i = 0; i < 8; i++) {
                int idx = tid + i * 256;
                int tile = idx >> 9, w = idx & 511, rr = w >> 2, c = w & 3;
                size_t off = (size_t)(k0 + c * 8);
                const __nv_bfloat16* src =
                    (tile == 0) ? Ah + (size_t)sm_row[rr] * KTOT + off :
                    (tile == 1) ? Al + (size_t)sm_row[rr] * KTOT + off :
                    (tile == 2) ? Bh + (size_t)rr * KTOT + off :
                                  Bl + (size_t)rr * KTOT + off;
                pf[i] = *(const uint4*)src;
            }
        }
        // compute: two k16 steps
#pragma unroll
        for (int ks = 0; ks < 2; ks++) {
            int kb = ks * 32 + q * 4;
            uint32_t ah[4][4], al[4][4];
#pragma unroll
            for (int mt = 0; mt < 4; mt++) {
                const char* p = sm + (wm * 64 + mt * 16 + g) * PADB + kb;
                ah[mt][0] = *(const uint32_t*)(p);
                ah[mt][1] = *(const uint32_t*)(p + 8 * PADB);
                ah[mt][2] = *(const uint32_t*)(p + 16);
                ah[mt][3] = *(const uint32_t*)(p + 8 * PADB + 16);
                const char* p2 = p + TILE_B;
                al[mt][0] = *(const uint32_t*)(p2);
                al[mt][1] = *(const uint32_t*)(p2 + 8 * PADB);
                al[mt][2] = *(const uint32_t*)(p2 + 16);
                al[mt][3] = *(const uint32_t*)(p2 + 8 * PADB + 16);
            }
#pragma unroll
            for (int nt = 0; nt < 4; nt++) {
                const char* pb = sm + 2 * TILE_B + (wn * 32 + nt * 8 + g) * PADB + kb;
                uint32_t bh0 = *(const uint32_t*)(pb);
                uint32_t bh1 = *(const uint32_t*)(pb + 16);
                uint32_t bl0 = *(const uint32_t*)(pb + TILE_B);
                uint32_t bl1 = *(const uint32_t*)(pb + TILE_B + 16);
#pragma unroll
                for (int mt = 0; mt < 4; mt++) {
                    MMA16816(acc[mt][nt], ah[mt], bh0, bh1);
                    MMA16816(acc[mt][nt], ah[mt], bl0, bl1);
                    MMA16816(acc[mt][nt], al[mt], bh0, bh1);
                }
            }
        }
        __syncthreads();
    }

    // -------- epilogue --------
    // accumulator: c0,c1 -> row g, cols q*2,q*2+1 ; c2,c3 -> row g+8
    int rloc = wm * 64 + g;
    int cg0  = col0 + wn * 32 + q * 2;
#pragma unroll
    for (int mt = 0; mt < 4; mt++) {
#pragma unroll
        for (int half = 0; half < 2; half++) {
            int rb = rloc + mt * 16 + half * 8;
            int p = sm_pair[rb];
            if (p < 0) continue;
            if (FFN1) {
                __nv_bfloat16* hh = d_hhi + (size_t)p * DFF;
                __nv_bfloat16* hl = d_hlo + (size_t)p * DFF;
#pragma unroll
                for (int nt = 0; nt < 4; nt++) {
                    int c = cg0 + nt * 8;
                    float v0 = gelu_exact(acc[mt][nt][half * 2 + 0] + be[c]);
                    float v1 = gelu_exact(acc[mt][nt][half * 2 + 1] + be[c + 1]);
                    __nv_bfloat16 h0, l0, h1, l1;
                    bsplit(v0, h0, l0); bsplit(v1, h1, l1);
                    __nv_bfloat162 ph; ph.x = h0; ph.y = h1;
                    __nv_bfloat162 pl; pl.x = l0; pl.y = l1;
                    *(__nv_bfloat162*)(hh + c) = ph;
                    *(__nv_bfloat162*)(hl + c) = pl;
                }
            } else {
                int t = p >> 1;
                float w = sm_w[rb];
                float* orow = outp + (size_t)t * DHID;
#pragma unroll
                for (int nt = 0; nt < 4; nt++) {
                    int c = cg0 + nt * 8;
                    atomicAdd(&orow[c],     w * (acc[mt][nt][half * 2 + 0] + be[c]));
                    atomicAdd(&orow[c + 1], w * (acc[mt][nt][half * 2 + 1] + be[c + 1]));
                }
            }
        }
    }
}

// -------------------- lb loss --------------------
__global__ void lb_kernel(float* __restrict__ out, int bsd, int out_size, int T) {
    if (threadIdx.x == 0 && blockIdx.x == 0) {
        float u[NE], s = 0.f;
#pragma unroll
        for (int e = 0; e < NE; e++) { u[e] = d_usage[e] / (float)T; s += u[e]; }
        float mean = s / (float)NE;
        float v = 0.f;
#pragma unroll
        for (int e = 0; e < NE; e++) { float d = u[e] - mean; v += d * d; }
        v = v / (float)(NE - 1) * 0.01f;
        if (out_size > bsd) out[bsd] = v;
    }
}

// -------------------- host --------------------
extern "C" void kernel_launch(void* const* d_in, const int* in_sizes, int n_in,
                              void* d_out, int out_size) {
    const float* x  = (const float*)d_in[0];
    const float* Wg = (const float*)d_in[1];
    const float* W1 = (const float*)d_in[2];
    const float* b1 = (const float*)d_in[3];
    const float* W2 = (const float*)d_in[4];
    const float* b2 = (const float*)d_in[5];
    float* out = (float*)d_out;

    int T = in_sizes[0] / DHID;   // 8192
    int bsd = T * DHID;
    int n4 = bsd / 4;

    init_kernel<<<(n4 + 255) / 256, 256>>>(out, n4);
    gate_kernel<<<(T * 32 + 255) / 256, 256>>>(x, Wg, T);

    conv_x<<<(T * DHID + 255) / 256, 256>>>(x, T * DHID);

    dim3 tb(32, 8);
    trans_conv<true><<<dim3(DFF / 32, DHID / 32, NE), tb>>>(W1);
    trans_conv<false><<<dim3(DHID / 32, DFF / 32, NE), tb>>>(W2);

    int mt = (T + BM - 1) / BM;   // 64
    ffn_mma<DHID, true><<<dim3(DFF / BN, mt, NE), 256>>>(b1, nullptr);
    ffn_mma<DFF, false><<<dim3(DHID / BN, mt, NE), 256>>>(b2, out);

    lb_kernel<<<1, 32>>>(out, bsd, out_size, T);
}

// round 15
// speedup vs baseline: 2.9140x; 1.0315x over previous
#include <cuda_runtime.h>
#include <cuda_bf16.h>
#include <math.h>
#include <stdint.h>

#define DHID 1024
#define DFF  4096
#define NE   8
#define TMAX 8192
#define BM 128
#define BN 128
#define BK 32
#define PADB 80                      // bytes per smem row (64 data + 16 pad; conflict-free)
#define TILE_B (128 * PADB)          // 10240 bytes per component tile
#define BUF_B  (4 * TILE_B)          // Ahi | Alo | Bhi | Blo = 40960 per stage
#define STAGES 4
#define SMEM_DYN (STAGES * BUF_B + 1536)

// -------------------- device scratch (16B aligned) --------------------
__device__ __align__(16) __nv_bfloat16 d_xhi[(size_t)TMAX * DHID];
__device__ __align__(16) __nv_bfloat16 d_xlo[(size_t)TMAX * DHID];
__device__ __align__(16) __nv_bfloat16 d_w1hi[(size_t)NE * DFF * DHID];  // [e][f][d]
__device__ __align__(16) __nv_bfloat16 d_w1lo[(size_t)NE * DFF * DHID];
__device__ __align__(16) __nv_bfloat16 d_w2hi[(size_t)NE * DHID * DFF]; // [e][d][f]
__device__ __align__(16) __nv_bfloat16 d_w2lo[(size_t)NE * DHID * DFF];
__device__ __align__(16) __nv_bfloat16 d_hhi[(size_t)(2 * TMAX) * DFF]; // pair-addressed
__device__ __align__(16) __nv_bfloat16 d_hlo[(size_t)(2 * TMAX) * DFF];
__device__ int   d_list [NE * TMAX];
__device__ float d_wlist[NE * TMAX];
__device__ int   d_cnt[NE];
__device__ float d_usage[NE];

// -------------------- helpers --------------------
__device__ __forceinline__ uint32_t smem_u32(const void* p) {
    uint32_t a;
    asm("{ .reg .u64 t; cvta.to.shared.u64 t, %1; cvt.u32.u64 %0, t; }" : "=r"(a) : "l"(p));
    return a;
}
__device__ __forceinline__ void cpasync16(uint32_t d, const void* s) {
    asm volatile("cp.async.cg.shared.global [%0], [%1], 16;" :: "r"(d), "l"(s));
}
#define CP_COMMIT() asm volatile("cp.async.commit_group;" ::: "memory")
#define CP_WAIT2()  asm volatile("cp.async.wait_group 2;" ::: "memory")

#define MMA16816(d, a, b0, b1) \
    asm volatile("mma.sync.aligned.m16n8k16.row.col.f32.bf16.bf16.f32 " \
        "{%0,%1,%2,%3},{%4,%5,%6,%7},{%8,%9},{%0,%1,%2,%3};" \
        : "+f"((d)[0]), "+f"((d)[1]), "+f"((d)[2]), "+f"((d)[3]) \
        : "r"((a)[0]), "r"((a)[1]), "r"((a)[2]), "r"((a)[3]), "r"(b0), "r"(b1))

__device__ __forceinline__ float gelu_exact(float v) {
    return 0.5f * v * (1.f + erff(v * 0.70710678118654752f));
}
__device__ __forceinline__ void bsplit(float v, __nv_bfloat16& h, __nv_bfloat16& l) {
    h = __float2bfloat16(v);
    l = __float2bfloat16(v - __bfloat162float(h));
}

// -------------------- init --------------------
__global__ void init_kernel(float* __restrict__ out, int n4) {
    int i = blockIdx.x * blockDim.x + threadIdx.x;
    if (i < NE) { d_cnt[i] = 0; d_usage[i] = 0.f; }
    if (i < n4) ((float4*)out)[i] = make_float4(0.f, 0.f, 0.f, 0.f);
}

// -------------------- gating --------------------
__global__ void gate_kernel(const float* __restrict__ x,
                            const float* __restrict__ Wg, int T) {
    int gwarp = (blockIdx.x * blockDim.x + threadIdx.x) >> 5;
    int lane  = threadIdx.x & 31;
    if (gwarp >= T) return;
    const float* xr = x + (size_t)gwarp * DHID;
    float acc[NE];
#pragma unroll
    for (int e = 0; e < NE; e++) acc[e] = 0.f;
    for (int d = lane; d < DHID; d += 32) {
        float xv = xr[d];
#pragma unroll
        for (int e = 0; e < NE; e++) acc[e] += xv * Wg[e * DHID + d];
    }
#pragma unroll
    for (int e = 0; e < NE; e++)
#pragma unroll
        for (int off = 16; off; off >>= 1)
            acc[e] += __shfl_xor_sync(0xffffffffu, acc[e], off);
    if (lane == 0) {
        float v0 = acc[0], v1 = -INFINITY;
        int i0 = 0, i1 = -1;
#pragma unroll
        for (int e = 1; e < NE; e++) {
            float v = acc[e];
            if (v > v0) { v1 = v0; i1 = i0; v0 = v; i0 = e; }
            else if (v > v1) { v1 = v; i1 = e; }
        }
        float e1 = __expf(v1 - v0);
        float inv = 1.f / (1.f + e1);
        float w0 = inv, w1 = e1 * inv;
        atomicAdd(&d_usage[i0], w0);
        atomicAdd(&d_usage[i1], w1);
        int p0 = atomicAdd(&d_cnt[i0], 1);
        d_list [i0 * TMAX + p0] = gwarp * 2 + 0;
        d_wlist[i0 * TMAX + p0] = w0;
        int p1 = atomicAdd(&d_cnt[i1], 1);
        d_list [i1 * TMAX + p1] = gwarp * 2 + 1;
        d_wlist[i1 * TMAX + p1] = w1;
    }
}

// -------------------- x -> bf16 hi/lo --------------------
__global__ void conv_x(const float* __restrict__ x, int n) {
    int i = blockIdx.x * blockDim.x + threadIdx.x;
    if (i >= n) return;
    float v = x[i];
    __nv_bfloat16 h, l; bsplit(v, h, l);
    d_xhi[i] = h; d_xlo[i] = l;
}

// -------- W [e][R][C] -> W^T [e][C][R], bf16 hi/lo split --------
template<bool ISW1>
__global__ void trans_conv(const float* __restrict__ in) {
    const int R = ISW1 ? DHID : DFF;
    const int C = ISW1 ? DFF : DHID;
    __nv_bfloat16* oh = ISW1 ? d_w1hi : d_w2hi;
    __nv_bfloat16* ol = ISW1 ? d_w1lo : d_w2lo;
    __shared__ float t[32][33];
    int e = blockIdx.z;
    const float* ip = in + (size_t)e * R * C;
    size_t ob = (size_t)e * R * C;
    int c0 = blockIdx.x * 32, r0 = blockIdx.y * 32;
    int tx = threadIdx.x, ty = threadIdx.y;
#pragma unroll
    for (int i = 0; i < 32; i += 8)
        t[ty + i][tx] = ip[(size_t)(r0 + ty + i) * C + c0 + tx];
    __syncthreads();
#pragma unroll
    for (int i = 0; i < 32; i += 8) {
        float v = t[tx][ty + i];
        __nv_bfloat16 h, l; bsplit(v, h, l);
        size_t o = ob + (size_t)(c0 + ty + i) * R + r0 + tx;
        oh[o] = h; ol[o] = l;
    }
}

// -------------------- fill one stage via cp.async --------------------
__device__ __forceinline__ void fill_stage(
    char* base, int tid, int k0,
    const __nv_bfloat16* __restrict__ Ah, const __nv_bfloat16* __restrict__ Al,
    const __nv_bfloat16* __restrict__ Bh, const __nv_bfloat16* __restrict__ Bl,
    const int* __restrict__ sm_row, int KTOT)
{
#pragma unroll
    for (int i = 0; i < 8; i++) {
        int idx = tid + i * 256;
        int tile = idx >> 9, w = idx & 511, rr = w >> 2, c = w & 3;
        size_t off = (size_t)(k0 + c * 8);
        const __nv_bfloat16* src =
            (tile == 0) ? Ah + (size_t)sm_row[rr] * KTOT + off :
            (tile == 1) ? Al + (size_t)sm_row[rr] * KTOT + off :
            (tile == 2) ? Bh + (size_t)rr * KTOT + off :
                          Bl + (size_t)rr * KTOT + off;
        uint32_t dst = smem_u32(base + tile * TILE_B + rr * PADB + c * 16);
        cpasync16(dst, src);
    }
}

// -------------------- fused FFN GEMM: bf16x3 mma.sync, cp.async 4-stage --------------------
template<int KTOT, bool FFN1>
__global__ void __launch_bounds__(256)
ffn_mma(const float* __restrict__ bias, float* __restrict__ outp)
{
    extern __shared__ __align__(16) char smem[];
    int*   sm_row  = (int*)(smem + STAGES * BUF_B);
    int*   sm_pair = (int*)(smem + STAGES * BUF_B + 512);
    float* sm_w    = (float*)(smem + STAGES * BUF_B + 1024);

    int e = blockIdx.z;
    int n = d_cnt[e];
    int row0 = blockIdx.y * BM;
    if (row0 >= n) return;
    int col0 = blockIdx.x * BN;

    int tid = threadIdx.x;
    if (tid < BM) {
        int r = row0 + tid;
        int rc = (r < n) ? r : (n - 1);
        int p = d_list[e * TMAX + rc];
        sm_row[tid]  = FFN1 ? (p >> 1) : p;
        sm_pair[tid] = (r < n) ? p : -1;
        sm_w[tid]    = (r < n) ? d_wlist[e * TMAX + r] : 0.f;
    }
    __syncthreads();

    const __nv_bfloat16* Ah = FFN1 ? d_xhi : d_hhi;
    const __nv_bfloat16* Al = FFN1 ? d_xlo : d_hlo;
    const __nv_bfloat16* Bh = (FFN1 ? d_w1hi : d_w2hi) + (size_t)e * DFF * DHID + (size_t)col0 * KTOT;
    const __nv_bfloat16* Bl = (FFN1 ? d_w1lo : d_w2lo) + (size_t)e * DFF * DHID + (size_t)col0 * KTOT;
    const float* be = bias + (size_t)e * (FFN1 ? DFF : DHID);

    float acc[4][4][4] = {};

    const int KT = KTOT / BK;
    int lane = tid & 31, wid = tid >> 5;
    int wm = wid >> 2, wn = wid & 3;              // 2(m) x 4(n) warps; warp tile 64x32
    int g = lane >> 2, q = lane & 3;

    // prologue: 3 stages in flight
#pragma unroll
    for (int s = 0; s < STAGES - 1; s++) {
        fill_stage(smem + s * BUF_B, tid, s * BK, Ah, Al, Bh, Bl, sm_row, KTOT);
        CP_COMMIT();
    }

    for (int it = 0; it < KT; it++) {
        CP_WAIT2();                 // stage `it` resident (it+1, it+2 may be in flight)
        __syncthreads();            // all warps done with compute(it-1); data visible
        if (it + STAGES - 1 < KT)
            fill_stage(smem + ((it + STAGES - 1) % STAGES) * BUF_B, tid,
                       (it + STAGES - 1) * BK, Ah, Al, Bh, Bl, sm_row, KTOT);
        CP_COMMIT();                // commit (possibly empty) to keep group count in step

        char* bufb = smem + (it % STAGES) * BUF_B;
#pragma unroll
        for (int ks = 0; ks < 2; ks++) {
            int kb = ks * 32 + q * 4;
            uint32_t ah[4][4], al[4][4];
#pragma unroll
            for (int mt = 0; mt < 4; mt++) {
                const char* p = bufb + (wm * 64 + mt * 16 + g) * PADB + kb;
                ah[mt][0] = *(const uint32_t*)(p);
                ah[mt][1] = *(const uint32_t*)(p + 8 * PADB);
                ah[mt][2] = *(const uint32_t*)(p + 16);
                ah[mt][3] = *(const uint32_t*)(p + 8 * PADB + 16);
                const char* p2 = p + TILE_B;
                al[mt][0] = *(const uint32_t*)(p2);
                al[mt][1] = *(const uint32_t*)(p2 + 8 * PADB);
                al[mt][2] = *(const uint32_t*)(p2 + 16);
                al[mt][3] = *(const uint32_t*)(p2 + 8 * PADB + 16);
            }
#pragma unroll
            for (int nt = 0; nt < 4; nt++) {
                const char* pb = bufb + 2 * TILE_B + (wn * 32 + nt * 8 + g) * PADB + kb;
                uint32_t bh0 = *(const uint32_t*)(pb);
                uint32_t bh1 = *(const uint32_t*)(pb + 16);
                uint32_t bl0 = *(const uint32_t*)(pb + TILE_B);
                uint32_t bl1 = *(const uint32_t*)(pb + TILE_B + 16);
#pragma unroll
                for (int mt = 0; mt < 4; mt++) {
                    MMA16816(acc[mt][nt], ah[mt], bh0, bh1);
                    MMA16816(acc[mt][nt], ah[mt], bl0, bl1);
                    MMA16816(acc[mt][nt], al[mt], bh0, bh1);
                }
            }
        }
        // no trailing sync: next iter's sync precedes any overwrite of this buffer
    }

    // -------- epilogue --------
    int rloc = wm * 64 + g;
    int cg0  = col0 + wn * 32 + q * 2;
#pragma unroll
    for (int mt = 0; mt < 4; mt++) {
#pragma unroll
        for (int half = 0; half < 2; half++) {
            int rb = rloc + mt * 16 + half * 8;
            int p = sm_pair[rb];
            if (p < 0) continue;
            if (FFN1) {
                __nv_bfloat16* hh = d_hhi + (size_t)p * DFF;
                __nv_bfloat16* hl = d_hlo + (size_t)p * DFF;
#pragma unroll
                for (int nt = 0; nt < 4; nt++) {
                    int c = cg0 + nt * 8;
                    float v0 = gelu_exact(acc[mt][nt][half * 2 + 0] + be[c]);
                    float v1 = gelu_exact(acc[mt][nt][half * 2 + 1] + be[c + 1]);
                    __nv_bfloat16 h0, l0, h1, l1;
                    bsplit(v0, h0, l0); bsplit(v1, h1, l1);
                    __nv_bfloat162 ph; ph.x = h0; ph.y = h1;
                    __nv_bfloat162 pl; pl.x = l0; pl.y = l1;
                    *(__nv_bfloat162*)(hh + c) = ph;
                    *(__nv_bfloat162*)(hl + c) = pl;
                }
            } else {
                int t = p >> 1;
                float w = sm_w[rb];
                float* orow = outp + (size_t)t * DHID;
#pragma unroll
                for (int nt = 0; nt < 4; nt++) {
                    int c = cg0 + nt * 8;
                    atomicAdd(&orow[c],     w * (acc[mt][nt][half * 2 + 0] + be[c]));
                    atomicAdd(&orow[c + 1], w * (acc[mt][nt][half * 2 + 1] + be[c + 1]));
                }
            }
        }
    }
}

// -------------------- lb loss --------------------
__global__ void lb_kernel(float* __restrict__ out, int bsd, int out_size, int T) {
    if (threadIdx.x == 0 && blockIdx.x == 0) {
        float u[NE], s = 0.f;
#pragma unroll
        for (int e = 0; e < NE; e++) { u[e] = d_usage[e] / (float)T; s += u[e]; }
        float mean = s / (float)NE;
        float v = 0.f;
#pragma unroll
        for (int e = 0; e < NE; e++) { float d = u[e] - mean; v += d * d; }
        v = v / (float)(NE - 1) * 0.01f;
        if (out_size > bsd) out[bsd] = v;
    }
}

// -------------------- host --------------------
extern "C" void kernel_launch(void* const* d_in, const int* in_sizes, int n_in,
                              void* d_out, int out_size) {
    const float* x  = (const float*)d_in[0];
    const float* Wg = (const float*)d_in[1];
    const float* W1 = (const float*)d_in[2];
    const float* b1 = (const float*)d_in[3];
    const float* W2 = (const float*)d_in[4];
    const float* b2 = (const float*)d_in[5];
    float* out = (float*)d_out;

    int T = in_sizes[0] / DHID;   // 8192
    int bsd = T * DHID;
    int n4 = bsd / 4;

    cudaFuncSetAttribute(ffn_mma<DHID, true>,  cudaFuncAttributeMaxDynamicSharedMemorySize, SMEM_DYN);
    cudaFuncSetAttribute(ffn_mma<DFF, false>,  cudaFuncAttributeMaxDynamicSharedMemorySize, SMEM_DYN);

    init_kernel<<<(n4 + 255) / 256, 256>>>(out, n4);
    gate_kernel<<<(T * 32 + 255) / 256, 256>>>(x, Wg, T);

    conv_x<<<(T * DHID + 255) / 256, 256>>>(x, T * DHID);

    dim3 tb(32, 8);
    trans_conv<true><<<dim3(DFF / 32, DHID / 32, NE), tb>>>(W1);
    trans_conv<false><<<dim3(DHID / 32, DFF / 32, NE), tb>>>(W2);

    int mt = (T + BM - 1) / BM;   // 64
    ffn_mma<DHID, true><<<dim3(DFF / BN, mt, NE), 256, SMEM_DYN>>>(b1, nullptr);
    ffn_mma<DFF, false><<<dim3(DHID / BN, mt, NE), 256, SMEM_DYN>>>(b2, out);

    lb_kernel<<<1, 32>>>(out, bsd, out_size, T);
}

// round 17
// speedup vs baseline: 3.4722x; 1.1916x over previous
#include <cuda_runtime.h>
#include <cuda_bf16.h>
#include <math.h>
#include <stdint.h>

#define DHID 1024
#define DFF  4096
#define NE   8
#define TMAX 8192
#define BM 128
#define BN 128
#define BK 32
#define PADB 80                      // bytes per smem row (64 data + 16 pad; conflict-free)
#define TILE_B (128 * PADB)          // 10240 bytes per component tile
#define BUF_B  (4 * TILE_B)          // Ahi | Alo | Bhi | Blo = 40960 per stage
#define STAGES 2
#define SMEM_DYN (STAGES * BUF_B + 1536)

// -------------------- device scratch (16B aligned) --------------------
__device__ __align__(16) __nv_bfloat16 d_xhi[(size_t)TMAX * DHID];
__device__ __align__(16) __nv_bfloat16 d_xlo[(size_t)TMAX * DHID];
__device__ __align__(16) __nv_bfloat16 d_w1hi[(size_t)NE * DFF * DHID];  // [e][f][d]
__device__ __align__(16) __nv_bfloat16 d_w1lo[(size_t)NE * DFF * DHID];
__device__ __align__(16) __nv_bfloat16 d_w2hi[(size_t)NE * DHID * DFF]; // [e][d][f]
__device__ __align__(16) __nv_bfloat16 d_w2lo[(size_t)NE * DHID * DFF];
__device__ __align__(16) __nv_bfloat16 d_hhi[(size_t)(2 * TMAX) * DFF]; // pair-addressed
__device__ __align__(16) __nv_bfloat16 d_hlo[(size_t)(2 * TMAX) * DFF];
__device__ int   d_list [NE * TMAX];
__device__ float d_wlist[NE * TMAX];
__device__ int   d_cnt[NE];
__device__ float d_usage[NE];

// -------------------- helpers --------------------
__device__ __forceinline__ uint32_t smem_u32(const void* p) {
    uint32_t a;
    asm("{ .reg .u64 t; cvta.to.shared.u64 t, %1; cvt.u32.u64 %0, t; }" : "=r"(a) : "l"(p));
    return a;
}
__device__ __forceinline__ void cpasync16(uint32_t d, const void* s) {
    asm volatile("cp.async.cg.shared.global [%0], [%1], 16;" :: "r"(d), "l"(s));
}
#define CP_COMMIT() asm volatile("cp.async.commit_group;" ::: "memory")
#define CP_WAIT1()  asm volatile("cp.async.wait_group 1;" ::: "memory")

#define MMA16816(d, a, b0, b1) \
    asm volatile("mma.sync.aligned.m16n8k16.row.col.f32.bf16.bf16.f32 " \
        "{%0,%1,%2,%3},{%4,%5,%6,%7},{%8,%9},{%0,%1,%2,%3};" \
        : "+f"((d)[0]), "+f"((d)[1]), "+f"((d)[2]), "+f"((d)[3]) \
        : "r"((a)[0]), "r"((a)[1]), "r"((a)[2]), "r"((a)[3]), "r"(b0), "r"(b1))

__device__ __forceinline__ float gelu_exact(float v) {
    return 0.5f * v * (1.f + erff(v * 0.70710678118654752f));
}
__device__ __forceinline__ void bsplit(float v, __nv_bfloat16& h, __nv_bfloat16& l) {
    h = __float2bfloat16(v);
    l = __float2bfloat16(v - __bfloat162float(h));
}

// -------------------- init --------------------
__global__ void init_kernel(float* __restrict__ out, int n4) {
    int i = blockIdx.x * blockDim.x + threadIdx.x;
    if (i < NE) { d_cnt[i] = 0; d_usage[i] = 0.f; }
    if (i < n4) ((float4*)out)[i] = make_float4(0.f, 0.f, 0.f, 0.f);
}

// -------------------- gating --------------------
__global__ void gate_kernel(const float* __restrict__ x,
                            const float* __restrict__ Wg, int T) {
    int gwarp = (blockIdx.x * blockDim.x + threadIdx.x) >> 5;
    int lane  = threadIdx.x & 31;
    if (gwarp >= T) return;
    const float* xr = x + (size_t)gwarp * DHID;
    float acc[NE];
#pragma unroll
    for (int e = 0; e < NE; e++) acc[e] = 0.f;
    for (int d = lane; d < DHID; d += 32) {
        float xv = xr[d];
#pragma unroll
        for (int e = 0; e < NE; e++) acc[e] += xv * Wg[e * DHID + d];
    }
#pragma unroll
    for (int e = 0; e < NE; e++)
#pragma unroll
        for (int off = 16; off; off >>= 1)
            acc[e] += __shfl_xor_sync(0xffffffffu, acc[e], off);
    if (lane == 0) {
        float v0 = acc[0], v1 = -INFINITY;
        int i0 = 0, i1 = -1;
#pragma unroll
        for (int e = 1; e < NE; e++) {
            float v = acc[e];
            if (v > v0) { v1 = v0; i1 = i0; v0 = v; i0 = e; }
            else if (v > v1) { v1 = v; i1 = e; }
        }
        float e1 = __expf(v1 - v0);
        float inv = 1.f / (1.f + e1);
        float w0 = inv, w1 = e1 * inv;
        atomicAdd(&d_usage[i0], w0);
        atomicAdd(&d_usage[i1], w1);
        int p0 = atomicAdd(&d_cnt[i0], 1);
        d_list [i0 * TMAX + p0] = gwarp * 2 + 0;
        d_wlist[i0 * TMAX + p0] = w0;
        int p1 = atomicAdd(&d_cnt[i1], 1);
        d_list [i1 * TMAX + p1] = gwarp * 2 + 1;
        d_wlist[i1 * TMAX + p1] = w1;
    }
}

// -------------------- x -> bf16 hi/lo --------------------
__global__ void conv_x(const float* __restrict__ x, int n) {
    int i = blockIdx.x * blockDim.x + threadIdx.x;
    if (i >= n) return;
    float v = x[i];
    __nv_bfloat16 h, l; bsplit(v, h, l);
    d_xhi[i] = h; d_xlo[i] = l;
}

// -------- W [e][R][C] -> W^T [e][C][R], bf16 hi/lo split --------
template<bool ISW1>
__global__ void trans_conv(const float* __restrict__ in) {
    const int R = ISW1 ? DHID : DFF;
    const int C = ISW1 ? DFF : DHID;
    __nv_bfloat16* oh = ISW1 ? d_w1hi : d_w2hi;
    __nv_bfloat16* ol = ISW1 ? d_w1lo : d_w2lo;
    __shared__ float t[32][33];
    int e = blockIdx.z;
    const float* ip = in + (size_t)e * R * C;
    size_t ob = (size_t)e * R * C;
    int c0 = blockIdx.x * 32, r0 = blockIdx.y * 32;
    int tx = threadIdx.x, ty = threadIdx.y;
#pragma unroll
    for (int i = 0; i < 32; i += 8)
        t[ty + i][tx] = ip[(size_t)(r0 + ty + i) * C + c0 + tx];
    __syncthreads();
#pragma unroll
    for (int i = 0; i < 32; i += 8) {
        float v = t[tx][ty + i];
        __nv_bfloat16 h, l; bsplit(v, h, l);
        size_t o = ob + (size_t)(c0 + ty + i) * R + r0 + tx;
        oh[o] = h; ol[o] = l;
    }
}

// -------------------- fill one stage via cp.async --------------------
__device__ __forceinline__ void fill_stage(
    char* base, int tid, int k0,
    const __nv_bfloat16* __restrict__ Ah, const __nv_bfloat16* __restrict__ Al,
    const __nv_bfloat16* __restrict__ Bh, const __nv_bfloat16* __restrict__ Bl,
    const int* __restrict__ sm_row, int KTOT)
{
#pragma unroll
    for (int i = 0; i < 8; i++) {
        int idx = tid + i * 256;
        int tile = idx >> 9, w = idx & 511, rr = w >> 2, c = w & 3;
        size_t off = (size_t)(k0 + c * 8);
        const __nv_bfloat16* src =
            (tile == 0) ? Ah + (size_t)sm_row[rr] * KTOT + off :
            (tile == 1) ? Al + (size_t)sm_row[rr] * KTOT + off :
            (tile == 2) ? Bh + (size_t)rr * KTOT + off :
                          Bl + (size_t)rr * KTOT + off;
        uint32_t dst = smem_u32(base + tile * TILE_B + rr * PADB + c * 16);
        cpasync16(dst, src);
    }
}

// -------------------- fused FFN GEMM: bf16x3 mma.sync, 2-stage, occ 2 --------------------
template<int KTOT, bool FFN1>
__global__ void __launch_bounds__(256, 2)
ffn_mma(const float* __restrict__ bias, float* __restrict__ outp)
{
    extern __shared__ __align__(16) char smem[];
    int*   sm_row  = (int*)(smem + STAGES * BUF_B);
    int*   sm_pair = (int*)(smem + STAGES * BUF_B + 512);
    float* sm_w    = (float*)(smem + STAGES * BUF_B + 1024);

    int e = blockIdx.z;
    int n = d_cnt[e];
    int row0 = blockIdx.y * BM;
    if (row0 >= n) return;
    int col0 = blockIdx.x * BN;

    int tid = threadIdx.x;
    if (tid < BM) {
        int r = row0 + tid;
        int rc = (r < n) ? r : (n - 1);
        int p = d_list[e * TMAX + rc];
        sm_row[tid]  = FFN1 ? (p >> 1) : p;
        sm_pair[tid] = (r < n) ? p : -1;
        sm_w[tid]    = (r < n) ? d_wlist[e * TMAX + r] : 0.f;
    }
    __syncthreads();

    const __nv_bfloat16* Ah = FFN1 ? d_xhi : d_hhi;
    const __nv_bfloat16* Al = FFN1 ? d_xlo : d_hlo;
    const __nv_bfloat16* Bh = (FFN1 ? d_w1hi : d_w2hi) + (size_t)e * DFF * DHID + (size_t)col0 * KTOT;
    const __nv_bfloat16* Bl = (FFN1 ? d_w1lo : d_w2lo) + (size_t)e * DFF * DHID + (size_t)col0 * KTOT;
    const float* be = bias + (size_t)e * (FFN1 ? DFF : DHID);

    float acc[4][4][4] = {};

    const int KT = KTOT / BK;
    int lane = tid & 31, wid = tid >> 5;
    int wm = wid >> 2, wn = wid & 3;              // 2(m) x 4(n) warps; warp tile 64x32
    int g = lane >> 2, q = lane & 3;

    // prologue: both stages in flight
    fill_stage(smem, tid, 0, Ah, Al, Bh, Bl, sm_row, KTOT);
    CP_COMMIT();
    fill_stage(smem + BUF_B, tid, BK, Ah, Al, Bh, Bl, sm_row, KTOT);
    CP_COMMIT();

    for (int it = 0; it < KT; it++) {
        CP_WAIT1();                 // stage `it` resident (stage it+1 may be in flight)
        __syncthreads();

        char* bufb = smem + (it & 1) * BUF_B;
#pragma unroll
        for (int ks = 0; ks < 2; ks++) {
            int kb = ks * 32 + q * 4;
            uint32_t ah[4][4], al[4][4];
#pragma unroll
            for (int mt = 0; mt < 4; mt++) {
                const char* p = bufb + (wm * 64 + mt * 16 + g) * PADB + kb;
                ah[mt][0] = *(const uint32_t*)(p);
                ah[mt][1] = *(const uint32_t*)(p + 8 * PADB);
                ah[mt][2] = *(const uint32_t*)(p + 16);
                ah[mt][3] = *(const uint32_t*)(p + 8 * PADB + 16);
                const char* p2 = p + TILE_B;
                al[mt][0] = *(const uint32_t*)(p2);
                al[mt][1] = *(const uint32_t*)(p2 + 8 * PADB);
                al[mt][2] = *(const uint32_t*)(p2 + 16);
                al[mt][3] = *(const uint32_t*)(p2 + 8 * PADB + 16);
            }
#pragma unroll
            for (int nt = 0; nt < 4; nt++) {
                const char* pb = bufb + 2 * TILE_B + (wn * 32 + nt * 8 + g) * PADB + kb;
                uint32_t bh0 = *(const uint32_t*)(pb);
                uint32_t bh1 = *(const uint32_t*)(pb + 16);
                uint32_t bl0 = *(const uint32_t*)(pb + TILE_B);
                uint32_t bl1 = *(const uint32_t*)(pb + TILE_B + 16);
#pragma unroll
                for (int mt = 0; mt < 4; mt++) {
                    MMA16816(acc[mt][nt], ah[mt], bh0, bh1);
                    MMA16816(acc[mt][nt], ah[mt], bl0, bl1);
                    MMA16816(acc[mt][nt], al[mt], bh0, bh1);
                }
            }
        }
        __syncthreads();            // everyone done reading stage (it&1) before refill
        if (it + 2 < KT)
            fill_stage(smem + (it & 1) * BUF_B, tid, (it + 2) * BK, Ah, Al, Bh, Bl, sm_row, KTOT);
        CP_COMMIT();                // keep group count in lockstep (possibly empty)
    }

    // -------- epilogue --------
    int rloc = wm * 64 + g;
    int cg0  = col0 + wn * 32 + q * 2;
#pragma unroll
    for (int mt = 0; mt < 4; mt++) {
#pragma unroll
        for (int half = 0; half < 2; half++) {
            int rb = rloc + mt * 16 + half * 8;
            int p = sm_pair[rb];
            if (p < 0) continue;
            if (FFN1) {
                __nv_bfloat16* hh = d_hhi + (size_t)p * DFF;
                __nv_bfloat16* hl = d_hlo + (size_t)p * DFF;
#pragma unroll
                for (int nt = 0; nt < 4; nt++) {
                    int c = cg0 + nt * 8;
                    float v0 = gelu_exact(acc[mt][nt][half * 2 + 0] + be[c]);
                    float v1 = gelu_exact(acc[mt][nt][half * 2 + 1] + be[c + 1]);
                    __nv_bfloat16 h0, l0, h1, l1;
                    bsplit(v0, h0, l0); bsplit(v1, h1, l1);
                    __nv_bfloat162 ph; ph.x = h0; ph.y = h1;
                    __nv_bfloat162 pl; pl.x = l0; pl.y = l1;
                    *(__nv_bfloat162*)(hh + c) = ph;
                    *(__nv_bfloat162*)(hl + c) = pl;
                }
            } else {
                int t = p >> 1;
                float w = sm_w[rb];
                float* orow = outp + (size_t)t * DHID;
#pragma unroll
                for (int nt = 0; nt < 4; nt++) {
                    int c = cg0 + nt * 8;
                    atomicAdd(&orow[c],     w * (acc[mt][nt][half * 2 + 0] + be[c]));
                    atomicAdd(&orow[c + 1], w * (acc[mt][nt][half * 2 + 1] + be[c + 1]));
                }
            }
        }
    }
}

// -------------------- lb loss --------------------
__global__ void lb_kernel(float* __restrict__ out, int bsd, int out_size, int T) {
    if (threadIdx.x == 0 && blockIdx.x == 0) {
        float u[NE], s = 0.f;
#pragma unroll
        for (int e = 0; e < NE; e++) { u[e] = d_usage[e] / (float)T; s += u[e]; }
        float mean = s / (float)NE;
        float v = 0.f;
#pragma unroll
        for (int e = 0; e < NE; e++) { float d = u[e] - mean; v += d * d; }
        v = v / (float)(NE - 1) * 0.01f;
        if (out_size > bsd) out[bsd] = v;
    }
}

// -------------------- host --------------------
extern "C" void kernel_launch(void* const* d_in, const int* in_sizes, int n_in,
                              void* d_out, int out_size) {
    const float* x  = (const float*)d_in[0];
    const float* Wg = (const float*)d_in[1];
    const float* W1 = (const float*)d_in[2];
    const float* b1 = (const float*)d_in[3];
    const float* W2 = (const float*)d_in[4];
    const float* b2 = (const float*)d_in[5];
    float* out = (float*)d_out;

    int T = in_sizes[0] / DHID;   // 8192
    int bsd = T * DHID;
    int n4 = bsd / 4;

    cudaFuncSetAttribute(ffn_mma<DHID, true>,  cudaFuncAttributeMaxDynamicSharedMemorySize, SMEM_DYN);
    cudaFuncSetAttribute(ffn_mma<DFF, false>,  cudaFuncAttributeMaxDynamicSharedMemorySize, SMEM_DYN);

    init_kernel<<<(n4 + 255) / 256, 256>>>(out, n4);
    gate_kernel<<<(T * 32 + 255) / 256, 256>>>(x, Wg, T);

    conv_x<<<(T * DHID + 255) / 256, 256>>>(x, T * DHID);

    dim3 tb(32, 8);
    trans_conv<true><<<dim3(DFF / 32, DHID / 32, NE), tb>>>(W1);
    trans_conv<false><<<dim3(DHID / 32, DFF / 32, NE), tb>>>(W2);

    int mt = (T + BM - 1) / BM;   // 64
    ffn_mma<DHID, true><<<dim3(DFF / BN, mt, NE), 256, SMEM_DYN>>>(b1, nullptr);
    ffn_mma<DFF, false><<<dim3(DHID / BN, mt, NE), 256, SMEM_DYN>>>(b2, out);

    lb_kernel<<<1, 32>>>(out, bsd, out_size, T);
}